// round 2
// baseline (speedup 1.0000x reference)
#include <cuda_runtime.h>
#include <math.h>

// ---------------- problem constants ----------------
constexpr int Bq   = 64;     // batch
constexpr int NS   = 50;     // sentences per doc
constexpr int LS   = 60;     // sentence length
constexpr int LQ   = 32;     // question length
constexpr int D    = 300;    // embedding dim
constexpr int F    = 256;    // conv filters
constexpr int FS   = 3;      // filter size
constexpr int Vv   = 100000; // vocab
constexpr int QROWS = Bq * LQ;        // 2048
constexpr int SROWS = Bq * NS * LS;   // 192000
constexpr int LT    = NS * LS;        // 3000

// ---------------- device scratch (no allocs allowed) ----------------
__device__ float g_qe[QROWS * D];          // question embeddings
__device__ float g_qn[QROWS];              // |qe|
__device__ float g_se[SROWS * D];          // sentence embeddings (230 MB)
__device__ float g_sn[SROWS];              // |se|
__device__ float g_qc[QROWS * F];          // conv(question)
__device__ float g_qcn[QROWS];
__device__ float g_sc[SROWS * F];          // conv(sentences) (197 MB)
__device__ float g_scn[SROWS];
__device__ float g_simins[Bq * NS * LQ * LS];  // [b][n][q][l]
__device__ float g_simsen[Bq * NS * LQ * LS];
__device__ float g_sentrel[Bq * NS];

// ---------------- gather + norm ----------------
__global__ void gather_norm_kernel(const float* __restrict__ embeds,
                                   const int* __restrict__ tokens,
                                   int nrows, int which) {
    int warp = (blockIdx.x * blockDim.x + threadIdx.x) >> 5;
    int lane = threadIdx.x & 31;
    if (warp >= nrows) return;
    float* dst = which ? g_se : g_qe;
    float* nrm = which ? g_sn : g_qn;
    int tok = tokens[warp];
    const float* src = embeds + (size_t)tok * D;
    float* drow = dst + (size_t)warp * D;
    float ss = 0.0f;
    for (int i = lane; i < D; i += 32) {
        float v = src[i];
        drow[i] = v;
        ss += v * v;
    }
    #pragma unroll
    for (int o = 16; o; o >>= 1) ss += __shfl_xor_sync(0xffffffffu, ss, o);
    if (lane == 0) nrm[warp] = sqrtf(ss);
}

// ---------------- conv as GEMM: out[r,f] = sum_{t<3, l+t<SEG} X[r+t,:] . filt[f,t,:]
// Tiled SGEMM: BM=128, BN=128, BK=20, 256 threads, 8x8 register tile.
template<int SEGLEN>
__global__ void __launch_bounds__(256) conv_gemm_kernel(const float* __restrict__ filt,
                                                        int R, int which) {
    const float* X  = which ? g_se : g_qe;
    float*      out = which ? g_sc : g_qc;

    __shared__ float As[20 * 132];
    __shared__ float Bs[20 * 132];

    int tid = threadIdx.x;
    int bm = blockIdx.x, bn = blockIdx.y;
    int tx = tid & 15, ty = tid >> 4;

    float acc[8][8];
    #pragma unroll
    for (int i = 0; i < 8; ++i)
        #pragma unroll
        for (int j = 0; j < 8; ++j) acc[i][j] = 0.0f;

    int rc    = tid >> 1;          // 0..127 : row (A) / col (B) loaded by this thread
    int kbase = (tid & 1) * 10;    // half of the 20-wide k-chunk
    int g = bm * 128 + rc;         // output row
    int l = g % SEGLEN;            // position within segment
    int c = bn * 128 + rc;         // filter index (always < 256)

    for (int t = 0; t < FS; ++t) {
        bool aval = (g < R) && (l + t < SEGLEN);
        const float* aptr = X + (size_t)(g + t) * D;
        const float* bptr = filt + (size_t)c * (FS * D) + t * D;
        for (int k0 = 0; k0 < D; k0 += 20) {
            __syncthreads();
            #pragma unroll
            for (int j = 0; j < 10; ++j) {
                int kk = kbase + j;
                As[kk * 132 + rc] = aval ? aptr[k0 + kk] : 0.0f;
                Bs[kk * 132 + rc] = bptr[k0 + kk];
            }
            __syncthreads();
            #pragma unroll
            for (int kk = 0; kk < 20; ++kk) {
                float4 a0 = *(const float4*)&As[kk * 132 + ty * 8];
                float4 a1 = *(const float4*)&As[kk * 132 + ty * 8 + 4];
                float4 b0 = *(const float4*)&Bs[kk * 132 + tx * 8];
                float4 b1 = *(const float4*)&Bs[kk * 132 + tx * 8 + 4];
                float av[8] = {a0.x, a0.y, a0.z, a0.w, a1.x, a1.y, a1.z, a1.w};
                float bv[8] = {b0.x, b0.y, b0.z, b0.w, b1.x, b1.y, b1.z, b1.w};
                #pragma unroll
                for (int i = 0; i < 8; ++i)
                    #pragma unroll
                    for (int j = 0; j < 8; ++j)
                        acc[i][j] += av[i] * bv[j];
            }
        }
    }

    #pragma unroll
    for (int i = 0; i < 8; ++i) {
        int gr = bm * 128 + ty * 8 + i;
        if (gr < R) {
            float* orow = out + (size_t)gr * F + bn * 128 + tx * 8;
            float4 v0 = make_float4(acc[i][0], acc[i][1], acc[i][2], acc[i][3]);
            float4 v1 = make_float4(acc[i][4], acc[i][5], acc[i][6], acc[i][7]);
            *(float4*)(orow)     = v0;
            *(float4*)(orow + 4) = v1;
        }
    }
}

// ---------------- row norms over F=256 ----------------
__global__ void rownorm_kernel(int R, int which) {
    const float* X = which ? g_sc : g_qc;
    float*     nrm = which ? g_scn : g_qcn;
    int warp = (blockIdx.x * blockDim.x + threadIdx.x) >> 5;
    int lane = threadIdx.x & 31;
    if (warp >= R) return;
    const float* row = X + (size_t)warp * F;
    float4 a = *(const float4*)&row[lane * 4];
    float4 b = *(const float4*)&row[128 + lane * 4];
    float ss = a.x * a.x + a.y * a.y + a.z * a.z + a.w * a.w
             + b.x * b.x + b.y * b.y + b.z * b.z + b.w * b.w;
    #pragma unroll
    for (int o = 16; o; o >>= 1) ss += __shfl_xor_sync(0xffffffffu, ss, o);
    if (lane == 0) nrm[warp] = sqrtf(ss);
}

// ---------------- cosine sim: per (b, l-chunk of 512): 32 q x 512 l dots over KD
// 256 threads = (tx:32, ty:8). thread tile: 4 q x 16 l (4 groups of float4).
template<int KD, int KC, int WHICH>
__global__ void __launch_bounds__(256) sim_kernel() {
    const float* Q  = WHICH ? g_qc  : g_qe;
    const float* S  = WHICH ? g_sc  : g_se;
    const float* qn = WHICH ? g_qcn : g_qn;
    const float* sn = WHICH ? g_scn : g_sn;
    float*      sim = WHICH ? g_simsen : g_simins;

    constexpr int SROW_F4 = KC / 4;
    constexpr int CHUNKS  = KD / KC;
    __shared__ float Qs[KC * 32];
    __shared__ float Ss[KC * 516];

    int b     = blockIdx.y;
    int lbase = blockIdx.x * 512;
    int tid   = threadIdx.x;
    int tx = tid & 31, ty = tid >> 5;

    const float* Qb = Q + (size_t)b * LQ * KD;
    const float* Sb = S + (size_t)b * LT * KD;

    float acc[4][16];
    #pragma unroll
    for (int i = 0; i < 4; ++i)
        #pragma unroll
        for (int j = 0; j < 16; ++j) acc[i][j] = 0.0f;

    for (int ch = 0; ch < CHUNKS; ++ch) {
        int k0 = ch * KC;
        __syncthreads();
        // load Q tile (transposed)
        if (tid < 32 * SROW_F4) {
            int q = tid / SROW_F4, cc = tid % SROW_F4;
            float4 v = *(const float4*)&Qb[(size_t)q * KD + k0 + cc * 4];
            Qs[(cc * 4 + 0) * 32 + q] = v.x;
            Qs[(cc * 4 + 1) * 32 + q] = v.y;
            Qs[(cc * 4 + 2) * 32 + q] = v.z;
            Qs[(cc * 4 + 3) * 32 + q] = v.w;
        }
        // load S tile (transposed), zero-fill out of range
        #pragma unroll
        for (int i = 0; i < 2 * SROW_F4; ++i) {
            int flat = tid + 256 * i;
            int lo = flat / SROW_F4, cc = flat % SROW_F4;
            int gl = lbase + lo;
            float4 v = make_float4(0.f, 0.f, 0.f, 0.f);
            if (gl < LT) v = *(const float4*)&Sb[(size_t)gl * KD + k0 + cc * 4];
            Ss[(cc * 4 + 0) * 516 + lo] = v.x;
            Ss[(cc * 4 + 1) * 516 + lo] = v.y;
            Ss[(cc * 4 + 2) * 516 + lo] = v.z;
            Ss[(cc * 4 + 3) * 516 + lo] = v.w;
        }
        __syncthreads();
        #pragma unroll
        for (int kk = 0; kk < KC; ++kk) {
            float4 qv = *(const float4*)&Qs[kk * 32 + ty * 4];
            float qa[4] = {qv.x, qv.y, qv.z, qv.w};
            #pragma unroll
            for (int jj = 0; jj < 4; ++jj) {
                float4 sv = *(const float4*)&Ss[kk * 516 + jj * 128 + tx * 4];
                float sa[4] = {sv.x, sv.y, sv.z, sv.w};
                #pragma unroll
                for (int qq = 0; qq < 4; ++qq)
                    #pragma unroll
                    for (int ll = 0; ll < 4; ++ll)
                        acc[qq][jj * 4 + ll] += qa[qq] * sa[ll];
            }
        }
    }

    float qnv[4];
    #pragma unroll
    for (int qq = 0; qq < 4; ++qq) qnv[qq] = qn[b * LQ + ty * 4 + qq];

    #pragma unroll
    for (int jj = 0; jj < 4; ++jj)
        #pragma unroll
        for (int ll = 0; ll < 4; ++ll) {
            int gl = lbase + jj * 128 + tx * 4 + ll;
            if (gl < LT) {
                float snv = sn[b * LT + gl];
                int n = gl / LS, l = gl % LS;
                #pragma unroll
                for (int qq = 0; qq < 4; ++qq) {
                    size_t oidx = ((((size_t)b * NS + n) * LQ) + (ty * 4 + qq)) * LS + l;
                    sim[oidx] = acc[qq][jj * 4 + ll] / (qnv[qq] * snv);
                }
            }
        }
}

// ---------------- top-k pooling + per-q linear + sigmoid + mean over q ----------------
__device__ __forceinline__ void insert5(float* t, float v) {
    if (v > t[4]) {
        t[4] = v;
        #pragma unroll
        for (int i = 4; i > 0; --i) {
            if (t[i] > t[i - 1]) { float tmp = t[i - 1]; t[i - 1] = t[i]; t[i] = tmp; }
        }
    }
}

__global__ void pool_kernel(const int* __restrict__ question,
                            const int* __restrict__ sentences,
                            const float* __restrict__ W,
                            const float* __restrict__ bias,
                            float* __restrict__ out_sent) {
    int bn = blockIdx.x;     // b*NS + n
    int b  = bn / NS;
    int q  = threadIdx.x;    // 0..31
    bool qm = question[b * LQ + q] > 0;

    const float* si   = g_simins + ((size_t)bn * LQ + q) * LS;
    const float* ssen = g_simsen + ((size_t)bn * LQ + q) * LS;
    const int*   sent = sentences + (size_t)bn * LS;

    float ti[5] = {-INFINITY, -INFINITY, -INFINITY, -INFINITY, -INFINITY};
    float tc[5] = {-INFINITY, -INFINITY, -INFINITY, -INFINITY, -INFINITY};
    int cnt = 0;
    const float thr = (float)(1.0 - 1e-5);

    for (int l = 0; l < LS; ++l) {
        float m  = (qm && sent[l] > 0) ? 1.0f : 0.0f;
        float vi = si[l];
        if (vi >= thr) ++cnt;                 // oh channel uses UNMASKED sim
        insert5(ti, vi * m);
        insert5(tc, ssen[l] * m);
    }
    float insMean = (ti[0] + ti[1] + ti[2] + ti[3] + ti[4]) * 0.2f;
    float senMean = (tc[0] + tc[1] + tc[2] + tc[3] + tc[4]) * 0.2f;
    float ohMax   = (cnt > 0) ? 1.0f : 0.0f;
    float ohMean  = fminf((float)cnt, 5.0f) * 0.2f;

    float z = W[0] * ti[0] + W[1] * insMean + W[2] * tc[0] + W[3] * senMean
            + W[4] * ohMax + W[5] * ohMean + bias[0];
    float p = 1.0f / (1.0f + expf(-z));

    #pragma unroll
    for (int o = 16; o; o >>= 1) p += __shfl_xor_sync(0xffffffffu, p, o);
    if (q == 0) {
        float sr = p * (1.0f / (float)LQ);
        g_sentrel[bn] = sr;
        if (out_sent) out_sent[bn] = sr;
    }
}

// ---------------- doc max + BCE losses ----------------
__global__ void final_kernel(const int* __restrict__ tsents,
                             const int* __restrict__ tdocs,
                             float* __restrict__ out_loss,
                             float* __restrict__ out_doc) {
    __shared__ float red[256];
    __shared__ float docs_s[Bq];
    int tid = threadIdx.x;
    const float eps = 1e-7f;
    const float hi  = (float)(1.0 - 1e-7);

    float s1 = 0.0f;
    for (int i = tid; i < Bq * NS; i += 256) {
        float p = fminf(fmaxf(g_sentrel[i], eps), hi);
        float t = (float)tsents[i];
        s1 += t * logf(p) + (1.0f - t) * log1pf(-p);
    }
    red[tid] = s1;
    __syncthreads();
    for (int s = 128; s > 0; s >>= 1) {
        if (tid < s) red[tid] += red[tid + s];
        __syncthreads();
    }
    float bce1 = -red[0] / (float)(Bq * NS);
    __syncthreads();

    if (tid < Bq) {
        float m = -INFINITY;
        for (int n = 0; n < NS; ++n) m = fmaxf(m, g_sentrel[tid * NS + n]);
        docs_s[tid] = m;
        if (out_doc) out_doc[tid] = m;
    }
    __syncthreads();

    float s2 = 0.0f;
    if (tid < Bq) {
        float p = fminf(fmaxf(docs_s[tid], eps), hi);
        float t = (float)tdocs[tid];
        s2 = t * logf(p) + (1.0f - t) * log1pf(-p);
    }
    red[tid] = s2;
    __syncthreads();
    for (int s = 128; s > 0; s >>= 1) {
        if (tid < s) red[tid] += red[tid + s];
        __syncthreads();
    }
    if (tid == 0) {
        float bce2 = -red[0] / (float)Bq;
        out_loss[0] = 0.5f * (bce1 + bce2);
    }
}

// ---------------- host ----------------
extern "C" void kernel_launch(void* const* d_in, const int* in_sizes, int n_in,
                              void* d_out, int out_size) {
    const int *sentences = nullptr, *question = nullptr, *tsents = nullptr, *tdocs = nullptr;
    const float *embeds = nullptr, *filters = nullptr, *W = nullptr, *bias = nullptr;

    for (int i = 0; i < n_in; ++i) {
        switch (in_sizes[i]) {
            case SROWS:        sentences = (const int*)d_in[i];  break; // 192000
            case QROWS:        question  = (const int*)d_in[i];  break; // 2048
            case Bq * NS:      tsents    = (const int*)d_in[i];  break; // 3200
            case Bq:           tdocs     = (const int*)d_in[i];  break; // 64
            case Vv * D:       embeds    = (const float*)d_in[i]; break;
            case F * FS * D:   filters   = (const float*)d_in[i]; break; // 230400
            case 6:            W         = (const float*)d_in[i]; break;
            case 1:            bias      = (const float*)d_in[i]; break;
            default: break;
        }
    }

    float* out = (float*)d_out;
    float* out_sent = (out_size >= 1 + Bq * NS)      ? out + 1            : nullptr;
    float* out_doc  = (out_size >= 1 + Bq * NS + Bq) ? out + 1 + Bq * NS  : nullptr;

    // 1-2: gather embeddings + L2 norms
    gather_norm_kernel<<<(QROWS * 32 + 255) / 256, 256>>>(embeds, question, QROWS, 0);
    gather_norm_kernel<<<(SROWS * 32 + 255) / 256, 256>>>(embeds, sentences, SROWS, 1);

    // 3-4: causal-ish conv (forward window, zero-pad at segment end) as SGEMM
    conv_gemm_kernel<LQ><<<dim3(QROWS / 128, F / 128), 256>>>(filters, QROWS, 0);
    conv_gemm_kernel<LS><<<dim3(SROWS / 128, F / 128), 256>>>(filters, SROWS, 1);

    // 5-6: conv-output norms
    rownorm_kernel<<<(QROWS * 32 + 255) / 256, 256>>>(QROWS, 0);
    rownorm_kernel<<<(SROWS * 32 + 255) / 256, 256>>>(SROWS, 1);

    // 7-8: cosine similarity matrices
    sim_kernel<300, 12, 0><<<dim3((LT + 511) / 512, Bq), 256>>>();
    sim_kernel<256, 16, 1><<<dim3((LT + 511) / 512, Bq), 256>>>();

    // 9: top-k pooling + linear + sigmoid + mean over q
    pool_kernel<<<Bq * NS, 32>>>(question, sentences, W, bias, out_sent);

    // 10: doc max + BCE
    final_kernel<<<1, 256>>>(tsents, tdocs, out, out_doc);
}

// round 4
// speedup vs baseline: 1.7380x; 1.7380x over previous
#include <cuda_runtime.h>
#include <cuda_bf16.h>
#include <cstdint>
#include <math.h>

// ---------------- problem constants ----------------
constexpr int Bq   = 64;     // batch
constexpr int NS   = 50;     // sentences per doc
constexpr int LS   = 60;     // sentence length
constexpr int LQ   = 32;     // question length
constexpr int D    = 300;    // embedding dim
constexpr int F    = 256;    // conv filters
constexpr int FS   = 3;      // filter size
constexpr int Vv   = 100000; // vocab
constexpr int QROWS = Bq * LQ;        // 2048
constexpr int SROWS = Bq * NS * LS;   // 192000
constexpr int LT    = NS * LS;        // 3000

// ---------------- device scratch (no allocs allowed) ----------------
__device__ float g_qe[QROWS * D];          // question embeddings
__device__ float g_qn[QROWS];              // |qe|
__device__ float g_se[SROWS * D];          // sentence embeddings (230 MB)
__device__ float g_sn[SROWS];              // |se|
__device__ float g_qc[QROWS * F];          // conv(question)
__device__ float g_qcn[QROWS];
__device__ float g_sc[SROWS * F];          // conv(sentences) (197 MB)
__device__ float g_scn[SROWS];
__device__ float g_simins[Bq * NS * LQ * LS];  // [b][n][q][l]
__device__ float g_simsen[Bq * NS * LQ * LS];
__device__ float g_sentrel[Bq * NS];

// ---------------- gather + norm ----------------
__global__ void gather_norm_kernel(const float* __restrict__ embeds,
                                   const int* __restrict__ tokens,
                                   int nrows, int which) {
    int warp = (blockIdx.x * blockDim.x + threadIdx.x) >> 5;
    int lane = threadIdx.x & 31;
    if (warp >= nrows) return;
    float* dst = which ? g_se : g_qe;
    float* nrm = which ? g_sn : g_qn;
    int tok = tokens[warp];
    const float* src = embeds + (size_t)tok * D;
    float* drow = dst + (size_t)warp * D;
    float ss = 0.0f;
    for (int i = lane; i < D; i += 32) {
        float v = src[i];
        drow[i] = v;
        ss += v * v;
    }
    #pragma unroll
    for (int o = 16; o; o >>= 1) ss += __shfl_xor_sync(0xffffffffu, ss, o);
    if (lane == 0) nrm[warp] = sqrtf(ss);
}

// ============================================================================
// conv as GEMM on tensor cores (split-bf16 emulated fp32):
//   out[r,f] = sum_{t<3, l+t<SEG} X[r+t,:] . filt[f,t,:]
// Block tile 128x128, 8 warps (4M x 2N), warp tile 32x64, mma m16n8k16 bf16.
// a = a_hi + a_lo (bf16 split); D = Ahi*Bhi + Ahi*Blo + Alo*Bhi (fp32 accum).
// ============================================================================

__device__ __forceinline__ void mma_bf16(float& c0, float& c1, float& c2, float& c3,
                                         uint32_t a0, uint32_t a1, uint32_t a2, uint32_t a3,
                                         uint32_t b0, uint32_t b1) {
    asm volatile("mma.sync.aligned.m16n8k16.row.col.f32.bf16.bf16.f32 "
                 "{%0,%1,%2,%3},{%4,%5,%6,%7},{%8,%9},{%0,%1,%2,%3};"
                 : "+f"(c0), "+f"(c1), "+f"(c2), "+f"(c3)
                 : "r"(a0), "r"(a1), "r"(a2), "r"(a3), "r"(b0), "r"(b1));
}

// SMEM row stride: 18 bf16 (36 B = 9 banks; gcd(9,32)=1 -> conflict-friendly)
constexpr int SMS = 18;
constexpr int KCHUNKS = 19;           // ceil(300/16) per tap
constexpr int NCHUNK  = FS * KCHUNKS; // 57

template<int SEG>
__global__ void __launch_bounds__(256) conv_mma_kernel(const float* __restrict__ filt,
                                                       int R, int which) {
    const float* X  = which ? g_se : g_qe;
    float*      out = which ? g_sc : g_qc;

    __shared__ __align__(16) __nv_bfloat16 AsHi[128 * SMS];
    __shared__ __align__(16) __nv_bfloat16 AsLo[128 * SMS];
    __shared__ __align__(16) __nv_bfloat16 BsHi[128 * SMS];
    __shared__ __align__(16) __nv_bfloat16 BsLo[128 * SMS];

    const int tid  = threadIdx.x;
    const int lane = tid & 31;
    const int wid  = tid >> 5;
    const int wm   = (wid & 3) * 32;   // warp M offset (4 warps in M)
    const int wn   = (wid >> 2) * 64;  // warp N offset (2 warps in N)
    const int g    = lane >> 2;        // group id 0..7
    const int tig  = lane & 3;         // thread-in-group 0..3

    const int rbase = blockIdx.x * 128;
    const int fbase = blockIdx.y * 128;

    // loader role: each thread loads row (tid>>1), k-half ((tid&1)*8)
    const int arow  = tid >> 1;
    const int khalf = (tid & 1) * 8;
    const int gr    = rbase + arow;     // global X row
    const int lpos  = gr % SEG;         // position within segment
    const int gf    = fbase + arow;     // global filter row (always < 256)

    float acc[2][8][4];
    #pragma unroll
    for (int i = 0; i < 2; ++i)
        #pragma unroll
        for (int j = 0; j < 8; ++j)
            #pragma unroll
            for (int v = 0; v < 4; ++v) acc[i][j][v] = 0.0f;

    float fa[8], fb[8];

    // ---- chunk loader: chunk c -> tap t, k-offset kc ----
    auto load_chunk = [&](int c) {
        int t  = (c >= 2 * KCHUNKS) ? 2 : (c >= KCHUNKS ? 1 : 0);
        int kc = (c - t * KCHUNKS) * 16;
        int k0 = kc + khalf;
        bool full = (k0 + 7 < D);
        bool aval = (lpos + t) < SEG;   // forward conv window inside segment

        const float* ap = X + (size_t)(gr + t) * D + k0;
        if (aval && full) {
            float4 v0 = *(const float4*)ap;
            float4 v1 = *(const float4*)(ap + 4);
            fa[0]=v0.x; fa[1]=v0.y; fa[2]=v0.z; fa[3]=v0.w;
            fa[4]=v1.x; fa[5]=v1.y; fa[6]=v1.z; fa[7]=v1.w;
        } else {
            #pragma unroll
            for (int e = 0; e < 8; ++e)
                fa[e] = (aval && (k0 + e < D)) ? ap[e] : 0.0f;
        }

        const float* bp = filt + (size_t)gf * (FS * D) + t * D + k0;
        if (full) {
            float4 v0 = *(const float4*)bp;
            float4 v1 = *(const float4*)(bp + 4);
            fb[0]=v0.x; fb[1]=v0.y; fb[2]=v0.z; fb[3]=v0.w;
            fb[4]=v1.x; fb[5]=v1.y; fb[6]=v1.z; fb[7]=v1.w;
        } else {
            #pragma unroll
            for (int e = 0; e < 8; ++e)
                fb[e] = (k0 + e < D) ? bp[e] : 0.0f;
        }
    };

    // ---- store to smem with hi/lo split ----
    auto sts_chunk = [&]() {
        #pragma unroll
        for (int e = 0; e < 8; e += 2) {
            int idx = arow * SMS + khalf + e;
            __nv_bfloat16 h0 = __float2bfloat16(fa[e]);
            __nv_bfloat16 h1 = __float2bfloat16(fa[e + 1]);
            __nv_bfloat16 l0 = __float2bfloat16(fa[e]     - __bfloat162float(h0));
            __nv_bfloat16 l1 = __float2bfloat16(fa[e + 1] - __bfloat162float(h1));
            *(__nv_bfloat162*)&AsHi[idx] = __halves2bfloat162(h0, h1);
            *(__nv_bfloat162*)&AsLo[idx] = __halves2bfloat162(l0, l1);
            __nv_bfloat16 p0 = __float2bfloat16(fb[e]);
            __nv_bfloat16 p1 = __float2bfloat16(fb[e + 1]);
            __nv_bfloat16 q0 = __float2bfloat16(fb[e]     - __bfloat162float(p0));
            __nv_bfloat16 q1 = __float2bfloat16(fb[e + 1] - __bfloat162float(p1));
            *(__nv_bfloat162*)&BsHi[idx] = __halves2bfloat162(p0, p1);
            *(__nv_bfloat162*)&BsLo[idx] = __halves2bfloat162(q0, q1);
        }
    };

    const uint32_t* AH = (const uint32_t*)AsHi;
    const uint32_t* AL = (const uint32_t*)AsLo;
    const uint32_t* BH = (const uint32_t*)BsHi;
    const uint32_t* BL = (const uint32_t*)BsLo;
    constexpr int RS = SMS / 2;   // row stride in u32 units = 9

    load_chunk(0);
    for (int c = 0; c < NCHUNK; ++c) {
        sts_chunk();
        __syncthreads();
        if (c + 1 < NCHUNK) load_chunk(c + 1);   // overlap LDG with compute

        uint32_t ah[2][4], al[2][4];
        #pragma unroll
        for (int i = 0; i < 2; ++i) {
            int r0 = (wm + i * 16 + g) * RS + tig;
            int r8 = r0 + 8 * RS;
            ah[i][0] = AH[r0];     ah[i][1] = AH[r8];
            ah[i][2] = AH[r0 + 4]; ah[i][3] = AH[r8 + 4];
            al[i][0] = AL[r0];     al[i][1] = AL[r8];
            al[i][2] = AL[r0 + 4]; al[i][3] = AL[r8 + 4];
        }
        #pragma unroll
        for (int j = 0; j < 8; ++j) {
            int rb = (wn + j * 8 + g) * RS + tig;
            uint32_t bh0 = BH[rb], bh1 = BH[rb + 4];
            uint32_t bl0 = BL[rb], bl1 = BL[rb + 4];
            #pragma unroll
            for (int i = 0; i < 2; ++i) {
                float* cc = acc[i][j];
                mma_bf16(cc[0], cc[1], cc[2], cc[3],
                         ah[i][0], ah[i][1], ah[i][2], ah[i][3], bh0, bh1);
                mma_bf16(cc[0], cc[1], cc[2], cc[3],
                         ah[i][0], ah[i][1], ah[i][2], ah[i][3], bl0, bl1);
                mma_bf16(cc[0], cc[1], cc[2], cc[3],
                         al[i][0], al[i][1], al[i][2], al[i][3], bh0, bh1);
            }
        }
        __syncthreads();
    }

    // ---- epilogue: rows are multiples of 128 (R % 128 == 0), no bounds ----
    #pragma unroll
    for (int i = 0; i < 2; ++i) {
        int r0 = rbase + wm + i * 16 + g;
        #pragma unroll
        for (int j = 0; j < 8; ++j) {
            int col = fbase + wn + j * 8 + tig * 2;
            float* o0 = out + (size_t)r0 * F + col;
            *(float2*)o0 = make_float2(acc[i][j][0], acc[i][j][1]);
            *(float2*)(o0 + (size_t)8 * F) = make_float2(acc[i][j][2], acc[i][j][3]);
        }
    }
}

// ---------------- row norms over F=256 ----------------
__global__ void rownorm_kernel(int R, int which) {
    const float* X = which ? g_sc : g_qc;
    float*     nrm = which ? g_scn : g_qcn;
    int warp = (blockIdx.x * blockDim.x + threadIdx.x) >> 5;
    int lane = threadIdx.x & 31;
    if (warp >= R) return;
    const float* row = X + (size_t)warp * F;
    float4 a = *(const float4*)&row[lane * 4];
    float4 b = *(const float4*)&row[128 + lane * 4];
    float ss = a.x * a.x + a.y * a.y + a.z * a.z + a.w * a.w
             + b.x * b.x + b.y * b.y + b.z * b.z + b.w * b.w;
    #pragma unroll
    for (int o = 16; o; o >>= 1) ss += __shfl_xor_sync(0xffffffffu, ss, o);
    if (lane == 0) nrm[warp] = sqrtf(ss);
}

// ---------------- cosine sim: per (b, l-chunk of 512): 32 q x 512 l dots over KD
template<int KD, int KC, int WHICH>
__global__ void __launch_bounds__(256) sim_kernel() {
    const float* Q  = WHICH ? g_qc  : g_qe;
    const float* S  = WHICH ? g_sc  : g_se;
    const float* qn = WHICH ? g_qcn : g_qn;
    const float* sn = WHICH ? g_scn : g_sn;
    float*      sim = WHICH ? g_simsen : g_simins;

    constexpr int SROW_F4 = KC / 4;
    constexpr int CHUNKS  = KD / KC;
    __shared__ float Qs[KC * 32];
    __shared__ float Ss[KC * 516];

    int b     = blockIdx.y;
    int lbase = blockIdx.x * 512;
    int tid   = threadIdx.x;
    int tx = tid & 31, ty = tid >> 5;

    const float* Qb = Q + (size_t)b * LQ * KD;
    const float* Sb = S + (size_t)b * LT * KD;

    float acc[4][16];
    #pragma unroll
    for (int i = 0; i < 4; ++i)
        #pragma unroll
        for (int j = 0; j < 16; ++j) acc[i][j] = 0.0f;

    for (int ch = 0; ch < CHUNKS; ++ch) {
        int k0 = ch * KC;
        __syncthreads();
        if (tid < 32 * SROW_F4) {
            int q = tid / SROW_F4, cc = tid % SROW_F4;
            float4 v = *(const float4*)&Qb[(size_t)q * KD + k0 + cc * 4];
            Qs[(cc * 4 + 0) * 32 + q] = v.x;
            Qs[(cc * 4 + 1) * 32 + q] = v.y;
            Qs[(cc * 4 + 2) * 32 + q] = v.z;
            Qs[(cc * 4 + 3) * 32 + q] = v.w;
        }
        #pragma unroll
        for (int i = 0; i < 2 * SROW_F4; ++i) {
            int flat = tid + 256 * i;
            int lo = flat / SROW_F4, cc = flat % SROW_F4;
            int gl = lbase + lo;
            float4 v = make_float4(0.f, 0.f, 0.f, 0.f);
            if (gl < LT) v = *(const float4*)&Sb[(size_t)gl * KD + k0 + cc * 4];
            Ss[(cc * 4 + 0) * 516 + lo] = v.x;
            Ss[(cc * 4 + 1) * 516 + lo] = v.y;
            Ss[(cc * 4 + 2) * 516 + lo] = v.z;
            Ss[(cc * 4 + 3) * 516 + lo] = v.w;
        }
        __syncthreads();
        #pragma unroll
        for (int kk = 0; kk < KC; ++kk) {
            float4 qv = *(const float4*)&Qs[kk * 32 + ty * 4];
            float qa[4] = {qv.x, qv.y, qv.z, qv.w};
            #pragma unroll
            for (int jj = 0; jj < 4; ++jj) {
                float4 sv = *(const float4*)&Ss[kk * 516 + jj * 128 + tx * 4];
                float sa[4] = {sv.x, sv.y, sv.z, sv.w};
                #pragma unroll
                for (int qq = 0; qq < 4; ++qq)
                    #pragma unroll
                    for (int ll = 0; ll < 4; ++ll)
                        acc[qq][jj * 4 + ll] += qa[qq] * sa[ll];
            }
        }
    }

    float qnv[4];
    #pragma unroll
    for (int qq = 0; qq < 4; ++qq) qnv[qq] = qn[b * LQ + ty * 4 + qq];

    #pragma unroll
    for (int jj = 0; jj < 4; ++jj)
        #pragma unroll
        for (int ll = 0; ll < 4; ++ll) {
            int gl = lbase + jj * 128 + tx * 4 + ll;
            if (gl < LT) {
                float snv = sn[b * LT + gl];
                int n = gl / LS, l = gl % LS;
                #pragma unroll
                for (int qq = 0; qq < 4; ++qq) {
                    size_t oidx = ((((size_t)b * NS + n) * LQ) + (ty * 4 + qq)) * LS + l;
                    sim[oidx] = acc[qq][jj * 4 + ll] / (qnv[qq] * snv);
                }
            }
        }
}

// ---------------- top-k pooling + per-q linear + sigmoid + mean over q ----------------
__device__ __forceinline__ void insert5(float* t, float v) {
    if (v > t[4]) {
        t[4] = v;
        #pragma unroll
        for (int i = 4; i > 0; --i) {
            if (t[i] > t[i - 1]) { float tmp = t[i - 1]; t[i - 1] = t[i]; t[i] = tmp; }
        }
    }
}

__global__ void pool_kernel(const int* __restrict__ question,
                            const int* __restrict__ sentences,
                            const float* __restrict__ W,
                            const float* __restrict__ bias,
                            float* __restrict__ out_sent) {
    int bn = blockIdx.x;     // b*NS + n
    int b  = bn / NS;
    int q  = threadIdx.x;    // 0..31
    bool qm = question[b * LQ + q] > 0;

    const float* si   = g_simins + ((size_t)bn * LQ + q) * LS;
    const float* ssen = g_simsen + ((size_t)bn * LQ + q) * LS;
    const int*   sent = sentences + (size_t)bn * LS;

    float ti[5] = {-INFINITY, -INFINITY, -INFINITY, -INFINITY, -INFINITY};
    float tc[5] = {-INFINITY, -INFINITY, -INFINITY, -INFINITY, -INFINITY};
    int cnt = 0;
    const float thr = (float)(1.0 - 1e-5);

    for (int l = 0; l < LS; ++l) {
        float m  = (qm && sent[l] > 0) ? 1.0f : 0.0f;
        float vi = si[l];
        if (vi >= thr) ++cnt;                 // oh channel uses UNMASKED sim
        insert5(ti, vi * m);
        insert5(tc, ssen[l] * m);
    }
    float insMean = (ti[0] + ti[1] + ti[2] + ti[3] + ti[4]) * 0.2f;
    float senMean = (tc[0] + tc[1] + tc[2] + tc[3] + tc[4]) * 0.2f;
    float ohMax   = (cnt > 0) ? 1.0f : 0.0f;
    float ohMean  = fminf((float)cnt, 5.0f) * 0.2f;

    float z = W[0] * ti[0] + W[1] * insMean + W[2] * tc[0] + W[3] * senMean
            + W[4] * ohMax + W[5] * ohMean + bias[0];
    float p = 1.0f / (1.0f + expf(-z));

    #pragma unroll
    for (int o = 16; o; o >>= 1) p += __shfl_xor_sync(0xffffffffu, p, o);
    if (q == 0) {
        float sr = p * (1.0f / (float)LQ);
        g_sentrel[bn] = sr;
        if (out_sent) out_sent[bn] = sr;
    }
}

// ---------------- doc max + BCE losses ----------------
__global__ void final_kernel(const int* __restrict__ tsents,
                             const int* __restrict__ tdocs,
                             float* __restrict__ out_loss,
                             float* __restrict__ out_doc) {
    __shared__ float red[256];
    __shared__ float docs_s[Bq];
    int tid = threadIdx.x;
    const float eps = 1e-7f;
    const float hi  = (float)(1.0 - 1e-7);

    float s1 = 0.0f;
    for (int i = tid; i < Bq * NS; i += 256) {
        float p = fminf(fmaxf(g_sentrel[i], eps), hi);
        float t = (float)tsents[i];
        s1 += t * logf(p) + (1.0f - t) * log1pf(-p);
    }
    red[tid] = s1;
    __syncthreads();
    for (int s = 128; s > 0; s >>= 1) {
        if (tid < s) red[tid] += red[tid + s];
        __syncthreads();
    }
    float bce1 = -red[0] / (float)(Bq * NS);
    __syncthreads();

    if (tid < Bq) {
        float m = -INFINITY;
        for (int n = 0; n < NS; ++n) m = fmaxf(m, g_sentrel[tid * NS + n]);
        docs_s[tid] = m;
        if (out_doc) out_doc[tid] = m;
    }
    __syncthreads();

    float s2 = 0.0f;
    if (tid < Bq) {
        float p = fminf(fmaxf(docs_s[tid], eps), hi);
        float t = (float)tdocs[tid];
        s2 = t * logf(p) + (1.0f - t) * log1pf(-p);
    }
    red[tid] = s2;
    __syncthreads();
    for (int s = 128; s > 0; s >>= 1) {
        if (tid < s) red[tid] += red[tid + s];
        __syncthreads();
    }
    if (tid == 0) {
        float bce2 = -red[0] / (float)Bq;
        out_loss[0] = 0.5f * (bce1 + bce2);
    }
}

// ---------------- host ----------------
extern "C" void kernel_launch(void* const* d_in, const int* in_sizes, int n_in,
                              void* d_out, int out_size) {
    const int *sentences = nullptr, *question = nullptr, *tsents = nullptr, *tdocs = nullptr;
    const float *embeds = nullptr, *filters = nullptr, *W = nullptr, *bias = nullptr;

    for (int i = 0; i < n_in; ++i) {
        switch (in_sizes[i]) {
            case SROWS:        sentences = (const int*)d_in[i];  break; // 192000
            case QROWS:        question  = (const int*)d_in[i];  break; // 2048
            case Bq * NS:      tsents    = (const int*)d_in[i];  break; // 3200
            case Bq:           tdocs     = (const int*)d_in[i];  break; // 64
            case Vv * D:       embeds    = (const float*)d_in[i]; break;
            case F * FS * D:   filters   = (const float*)d_in[i]; break; // 230400
            case 6:            W         = (const float*)d_in[i]; break;
            case 1:            bias      = (const float*)d_in[i]; break;
            default: break;
        }
    }

    float* out = (float*)d_out;
    float* out_sent = (out_size >= 1 + Bq * NS)      ? out + 1            : nullptr;
    float* out_doc  = (out_size >= 1 + Bq * NS + Bq) ? out + 1 + Bq * NS  : nullptr;

    // 1-2: gather embeddings + L2 norms
    gather_norm_kernel<<<(QROWS * 32 + 255) / 256, 256>>>(embeds, question, QROWS, 0);
    gather_norm_kernel<<<(SROWS * 32 + 255) / 256, 256>>>(embeds, sentences, SROWS, 1);

    // 3-4: forward conv (zero-pad at segment end) as split-bf16 tensor-core GEMM
    conv_mma_kernel<LQ><<<dim3(QROWS / 128, F / 128), 256>>>(filters, QROWS, 0);
    conv_mma_kernel<LS><<<dim3(SROWS / 128, F / 128), 256>>>(filters, SROWS, 1);

    // 5-6: conv-output norms
    rownorm_kernel<<<(QROWS * 32 + 255) / 256, 256>>>(QROWS, 0);
    rownorm_kernel<<<(SROWS * 32 + 255) / 256, 256>>>(SROWS, 1);

    // 7-8: cosine similarity matrices
    sim_kernel<300, 12, 0><<<dim3((LT + 511) / 512, Bq), 256>>>();
    sim_kernel<256, 16, 1><<<dim3((LT + 511) / 512, Bq), 256>>>();

    // 9: top-k pooling + linear + sigmoid + mean over q
    pool_kernel<<<Bq * NS, 32>>>(question, sentences, W, bias, out_sent);

    // 10: doc max + BCE
    final_kernel<<<1, 256>>>(tsents, tdocs, out, out_doc);
}